// round 17
// baseline (speedup 1.0000x reference)
#include <cuda_runtime.h>
#include <cuda_fp16.h>
#include <math.h>
#include <stdint.h>

#define D   768
#define LL  103
#define RR  512
#define BBATCH 2
#define SSEQ 512
#define M_TOT (LL*RR)              /* 52736 */
#define INV_SQRT_D 0.03608439182435161f

/* ---------------- static device scratch (no allocation allowed) ------------- */
__device__ __align__(128) float  g_Wct[D*D];               /* (Wq @ Wk^T)*inv = Wc^T    */
__device__ __align__(128) __half g_fk2h[BBATCH*SSEQ*D];    /* half(output @ Wc + bkq')  */
__device__ __align__(16)  float4 g_colpack[BBATCH*SSEQ];   /* {sbias', vlaw, vaccu, vterm} */
__device__ float  g_u[5][D];
__device__ float  g_c[4];
__device__ __align__(16) float4 g_pre[BBATCH*M_TOT];       /* {law,accu,term,0} pre-act */
__device__ float  g_hax[BBATCH*LL];
__device__ float  g_htx[BBATCH*LL];

/* ---------------- PTX helpers ---------------------------------------------- */
__device__ __forceinline__ uint32_t smem_u32(const void* p) {
    uint32_t a;
    asm("{ .reg .u64 t; cvta.to.shared.u64 t, %1; cvt.u32.u64 %0, t; }" : "=r"(a) : "l"(p));
    return a;
}
__device__ __forceinline__ void cpa16(uint32_t saddr, const void* g) {
    asm volatile("cp.async.cg.shared.global [%0], [%1], 16;" :: "r"(saddr), "l"(g) : "memory");
}
__device__ __forceinline__ void mma_f16_16x8x16(float* d, const uint32_t* a, const uint32_t* b) {
    asm volatile(
        "mma.sync.aligned.m16n8k16.row.col.f32.f16.f16.f32 "
        "{%0,%1,%2,%3}, {%4,%5,%6,%7}, {%8,%9}, {%0,%1,%2,%3};"
        : "+f"(d[0]), "+f"(d[1]), "+f"(d[2]), "+f"(d[3])
        : "r"(a[0]), "r"(a[1]), "r"(a[2]), "r"(a[3]), "r"(b[0]), "r"(b[1]));
}
__device__ __forceinline__ void mma_tf32_16x8x8(float* d, const uint32_t* a, const uint32_t* b) {
    asm volatile(
        "mma.sync.aligned.m16n8k8.row.col.f32.tf32.tf32.f32 "
        "{%0,%1,%2,%3}, {%4,%5,%6,%7}, {%8,%9}, {%0,%1,%2,%3};"
        : "+f"(d[0]), "+f"(d[1]), "+f"(d[2]), "+f"(d[3])
        : "r"(a[0]), "r"(a[1]), "r"(a[2]), "r"(a[3]), "r"(b[0]), "r"(b[1]));
}
__device__ __forceinline__ void ldsm_x4(uint32_t* r, uint32_t addr) {
    asm volatile("ldmatrix.sync.aligned.m8n8.x4.shared.b16 {%0,%1,%2,%3}, [%4];"
                 : "=r"(r[0]), "=r"(r[1]), "=r"(r[2]), "=r"(r[3]) : "r"(addr));
}
__device__ __forceinline__ uint32_t pack_h2(float2 f) {
    __half2 h = __floats2half2_rn(f.x, f.y);
    return *(uint32_t*)&h;
}
/* split fp32 into tf32-exact hi + residual lo (3xTF32 compensation) */
__device__ __forceinline__ void tf32_split(uint32_t u, uint32_t& hi, uint32_t& lo) {
    hi = u & 0xFFFFE000u;
    lo = __float_as_uint(__uint_as_float(u) - __uint_as_float(hi));
}

/* ---------------- tiny precompute kernels (warp-per-dot) -------------------- */
__global__ void k_vecs(const float* __restrict__ Wv, const float* __restrict__ Wk,
                       const float* __restrict__ Wq,
                       const float* __restrict__ wl, const float* __restrict__ wa,
                       const float* __restrict__ wt,
                       const float* __restrict__ bq, const float* __restrict__ bk) {
    int gid = blockIdx.x * 8 + (threadIdx.x >> 5);
    int lane = threadIdx.x & 31;
    int w = gid / D, e = gid % D;
    const float *row, *vec; float scale = 1.0f;
    if      (w == 0) { row = Wv + e*D; vec = wl; }
    else if (w == 1) { row = Wv + e*D; vec = wa; }
    else if (w == 2) { row = Wv + e*D; vec = wt; }
    else if (w == 3) { row = Wk + e*D; vec = bq; scale = INV_SQRT_D; }
    else             { row = Wq + e*D; vec = bk; scale = INV_SQRT_D; }
    float p = 0.f;
    for (int d = lane; d < D; d += 32) p += row[d] * vec[d];
    #pragma unroll
    for (int s = 16; s > 0; s >>= 1) p += __shfl_xor_sync(0xFFFFFFFFu, p, s);
    if (lane == 0) g_u[w][e] = p * scale;
}

__global__ void k_scal(const float* __restrict__ bk, const float* __restrict__ bq,
                       const float* __restrict__ bv,
                       const float* __restrict__ wl, const float* __restrict__ wa,
                       const float* __restrict__ wt) {
    int tid = threadIdx.x;
    float p0 = 0, p1 = 0, p2 = 0, p3 = 0;
    for (int d = tid; d < D; d += 256) {
        float b = bv[d];
        p0 += bk[d] * bq[d]; p1 += b * wl[d]; p2 += b * wa[d]; p3 += b * wt[d];
    }
    __shared__ float sm[4][256];
    sm[0][tid] = p0; sm[1][tid] = p1; sm[2][tid] = p2; sm[3][tid] = p3;
    __syncthreads();
    for (int s = 128; s > 0; s >>= 1) {
        if (tid < s) for (int c = 0; c < 4; c++) sm[c][tid] += sm[c][tid + s];
        __syncthreads();
    }
    if (tid == 0) {
        g_c[0] = sm[0][0] * INV_SQRT_D;
        g_c[1] = sm[1][0]; g_c[2] = sm[2][0]; g_c[3] = sm[3][0];
    }
}

/* ---- 3xTF32 mma GEMM (NT), 4-stage, KT=32, 512 thr (warp tile 16x16) ------- */
#define PKC      24
#define PST      9216
#define PBOFF    36864
#define SMEM_PREP 73728

__global__ __launch_bounds__(512) void k_wc_t(const float* __restrict__ A,
                                              const float* __restrict__ B) {
    extern __shared__ float smf[];
    uint32_t sa = smem_u32(smf);
    int tid = threadIdx.x, lane = tid & 31, wid = tid >> 5;
    int wm = wid >> 2, wn = wid & 3, g = lane >> 2, c = lane & 3;
    int i0 = blockIdx.y * 64, j0 = blockIdx.x * 64;
    float acc[2][4] = {};

#define LDWC(st, kc) do {                                                       \
        { int r = tid >> 3, s = tid & 7;                                        \
          cpa16(sa + (st)*PST + r*144 + s*16, A + (size_t)(i0+r)*D + (kc)*32 + s*4); } \
        { int r = tid >> 3, s = tid & 7;                                        \
          cpa16(sa + PBOFF + (st)*PST + r*144 + s*16, B + (size_t)(j0+r)*D + (kc)*32 + s*4); } \
        asm volatile("cp.async.commit_group;" ::: "memory");                    \
    } while (0)

    LDWC(0, 0); LDWC(1, 1); LDWC(2, 2);
    for (int kc = 0; kc < PKC; kc++) {
        asm volatile("cp.async.wait_group 2;" ::: "memory");
        __syncthreads();
        if (kc + 3 < PKC) LDWC((kc + 3) & 3, kc + 3);
        else asm volatile("cp.async.commit_group;" ::: "memory");
        const float* Aw = smf + (kc & 3) * (PST/4);
        const float* Bw = smf + (PBOFF + (kc & 3) * PST) / 4;
        #pragma unroll
        for (int s2 = 0; s2 < 4; s2++) {
            int kw = s2 * 8;
            uint32_t ah[4], al[4], bh[2][2], bl[2][2];
            {
                int m = wm * 16 + g;
                tf32_split(__float_as_uint(Aw[m * 36 + kw + c]),        ah[0], al[0]);
                tf32_split(__float_as_uint(Aw[(m + 8) * 36 + kw + c]),  ah[1], al[1]);
                tf32_split(__float_as_uint(Aw[m * 36 + kw + c + 4]),    ah[2], al[2]);
                tf32_split(__float_as_uint(Aw[(m + 8) * 36 + kw + c+4]),ah[3], al[3]);
            }
            #pragma unroll
            for (int nt = 0; nt < 2; nt++) {
                int n = wn * 16 + nt * 8 + g;
                tf32_split(__float_as_uint(Bw[n * 36 + kw + c]),     bh[nt][0], bl[nt][0]);
                tf32_split(__float_as_uint(Bw[n * 36 + kw + c + 4]), bh[nt][1], bl[nt][1]);
            }
            #pragma unroll
            for (int nt = 0; nt < 2; nt++) {
                mma_tf32_16x8x8(acc[nt], ah, bl[nt]);
                mma_tf32_16x8x8(acc[nt], al, bh[nt]);
                mma_tf32_16x8x8(acc[nt], ah, bh[nt]);
            }
        }
        __syncthreads();
    }
#undef LDWC
    #pragma unroll
    for (int nt = 0; nt < 2; nt++) {
        int r0 = i0 + wm * 16 + g;
        int col = j0 + wn * 16 + nt * 8 + 2 * c;
        g_Wct[(size_t)r0 * D + col]       = acc[nt][0] * INV_SQRT_D;
        g_Wct[(size_t)r0 * D + col + 1]   = acc[nt][1] * INV_SQRT_D;
        g_Wct[(size_t)(r0+8) * D + col]   = acc[nt][2] * INV_SQRT_D;
        g_Wct[(size_t)(r0+8) * D + col+1] = acc[nt][3] * INV_SQRT_D;
    }
}

/* ---- 3xTF32 mma GEMM (NT), 4-stage, KT=32, 512 thr: g_fk2h ----------------- */
__global__ __launch_bounds__(512) void k_fk2_t(const float* __restrict__ A) {
    extern __shared__ float smf[];
    uint32_t sa = smem_u32(smf);
    int tid = threadIdx.x, lane = tid & 31, wid = tid >> 5;
    int wm = wid >> 2, wn = wid & 3, g = lane >> 2, c = lane & 3;
    int i0 = blockIdx.y * 64, j0 = blockIdx.x * 64;
    float acc[2][4] = {};

#define LDFK(st, kc) do {                                                       \
        { int r = tid >> 3, s = tid & 7;                                        \
          cpa16(sa + (st)*PST + r*144 + s*16, A + (size_t)(i0+r)*D + (kc)*32 + s*4); } \
        { int r = tid >> 3, s = tid & 7;                                        \
          cpa16(sa + PBOFF + (st)*PST + r*144 + s*16, g_Wct + (size_t)(j0+r)*D + (kc)*32 + s*4); } \
        asm volatile("cp.async.commit_group;" ::: "memory");                    \
    } while (0)

    LDFK(0, 0); LDFK(1, 1); LDFK(2, 2);
    for (int kc = 0; kc < PKC; kc++) {
        asm volatile("cp.async.wait_group 2;" ::: "memory");
        __syncthreads();
        if (kc + 3 < PKC) LDFK((kc + 3) & 3, kc + 3);
        else asm volatile("cp.async.commit_group;" ::: "memory");
        const float* Aw = smf + (kc & 3) * (PST/4);
        const float* Bw = smf + (PBOFF + (kc & 3) * PST) / 4;
        #pragma unroll
        for (int s2 = 0; s2 < 4; s2++) {
            int kw = s2 * 8;
            uint32_t ah[4], al[4], bh[2][2], bl[2][2];
            {
                int m = wm * 16 + g;
                tf32_split(__float_as_uint(Aw[m * 36 + kw + c]),        ah[0], al[0]);
                tf32_split(__float_as_uint(Aw[(m + 8) * 36 + kw + c]),  ah[1], al[1]);
                tf32_split(__float_as_uint(Aw[m * 36 + kw + c + 4]),    ah[2], al[2]);
                tf32_split(__float_as_uint(Aw[(m + 8) * 36 + kw + c+4]),ah[3], al[3]);
            }
            #pragma unroll
            for (int nt = 0; nt < 2; nt++) {
                int n = wn * 16 + nt * 8 + g;
                tf32_split(__float_as_uint(Bw[n * 36 + kw + c]),     bh[nt][0], bl[nt][0]);
                tf32_split(__float_as_uint(Bw[n * 36 + kw + c + 4]), bh[nt][1], bl[nt][1]);
            }
            #pragma unroll
            for (int nt = 0; nt < 2; nt++) {
                mma_tf32_16x8x8(acc[nt], ah, bl[nt]);
                mma_tf32_16x8x8(acc[nt], al, bh[nt]);
                mma_tf32_16x8x8(acc[nt], ah, bh[nt]);
            }
        }
        __syncthreads();
    }
#undef LDFK
    #pragma unroll
    for (int nt = 0; nt < 2; nt++) {
        int r0 = i0 + wm * 16 + g;
        int col = j0 + wn * 16 + nt * 8 + 2 * c;
        float b0 = g_u[4][col], b1 = g_u[4][col + 1];
        g_fk2h[(size_t)r0 * D + col]       = __float2half_rn(acc[nt][0] + b0);
        g_fk2h[(size_t)r0 * D + col + 1]   = __float2half_rn(acc[nt][1] + b1);
        g_fk2h[(size_t)(r0+8) * D + col]   = __float2half_rn(acc[nt][2] + b0);
        g_fk2h[(size_t)(r0+8) * D + col+1] = __float2half_rn(acc[nt][3] + b1);
    }
}

/* per (b,s): sbias' (+mask), and the three v projections  (warp per row) */
__global__ void k_colpack(const float* __restrict__ outp, const int* __restrict__ mask) {
    int row = blockIdx.x * 8 + (threadIdx.x >> 5);
    int lane = threadIdx.x & 31;
    const float* x = outp + (size_t)row * D;
    float p0 = 0, p1 = 0, p2 = 0, p3 = 0;
    for (int d = lane; d < D; d += 32) {
        float xv = x[d];
        p0 += xv * g_u[3][d]; p1 += xv * g_u[0][d];
        p2 += xv * g_u[1][d]; p3 += xv * g_u[2][d];
    }
    #pragma unroll
    for (int s = 16; s > 0; s >>= 1) {
        p0 += __shfl_xor_sync(0xFFFFFFFFu, p0, s);
        p1 += __shfl_xor_sync(0xFFFFFFFFu, p1, s);
        p2 += __shfl_xor_sync(0xFFFFFFFFu, p2, s);
        p3 += __shfl_xor_sync(0xFFFFFFFFu, p3, s);
    }
    if (lane == 0) {
        float sb = p0 + g_c[0] + (1.0f - (float)mask[row]) * (-10000.0f);
        g_colpack[row] = make_float4(sb, p1 + g_c[1], p2 + g_c[2], p3 + g_c[3]);
    }
}

/* ------------- big fused kernel: fp16 mma.sync GEMM + softmax epilogue ------ */
/* A loaded as fp32 (laws) via cp.async, converted to fp16 during fragment     */
/* load (LDS.64 + cvt.rn.f16x2.f32). B fp16 via cp.async + ldmatrix x4 pairs.  */
#define KT        32               /* K elems per chunk */
#define NKC       (D/KT)           /* 24 */
#define A_ST      18432            /* 128 rows x 144 B (32 fp32 + 16 pad) */
#define B_ST      20480            /* 256 rows x 80 B  (32 fp16 + 16 pad) */
#define B_BASE    73728            /* 4*A_ST */
#define SCP_OFF_F 38912            /* byte 155648 / 4 */
#define RED_OFF_F 40960            /* byte 163840 / 4 */
#define SMEM_BIG  172032

__global__ __launch_bounds__(512) void k_big_h(const float* __restrict__ laws) {
    extern __shared__ float smf[];
    uint32_t sb = smem_u32(smf);
    int tid = threadIdx.x, lane = tid & 31, wid = tid >> 5;
    int wm = wid >> 2, wn = wid & 3;
    int g = lane >> 2, c = lane & 3;
    int b = blockIdx.y, m0 = blockIdx.x * 128;
    const __half* fk2b = g_fk2h + (size_t)b * SSEQ * D;

    float4* scp  = (float4*)(smf + SCP_OFF_F);
    float4* red4 = (float4*)(smf + RED_OFF_F);

    { const float4* gcp = g_colpack + b * SSEQ;
      for (int i = tid; i < SSEQ; i += 512) scp[i] = gcp[i]; }

    /* ldmatrix per-lane address offsets for B (relative to B stage base) */
    int l8 = lane & 7;
    uint32_t bOff4[4];
    #pragma unroll
    for (int j = 0; j < 4; j++)
        bOff4[j] = (uint32_t)((wn * 64 + j * 16 + ((lane >> 4) << 3) + l8) * 80
                              + (((lane >> 3) & 1) << 4));

    float rs[2][2][4];
    #pragma unroll
    for (int mt = 0; mt < 2; mt++)
        #pragma unroll
        for (int h = 0; h < 2; h++)
            #pragma unroll
            for (int e = 0; e < 4; e++) rs[mt][h][e] = 0.f;

#define LOADH(st, kc, n0) do {                                                 \
        uint32_t Ab = sb + (st) * A_ST;                                        \
        uint32_t Bb = sb + B_BASE + (st) * B_ST;                               \
        const float*  asrc = laws + (size_t)m0 * D + (kc) * KT;                \
        const __half* bsrc = fk2b + (size_t)(n0) * D + (kc) * KT;              \
        { int row = tid >> 2, seg = tid & 3;                                   \
          cpa16(Ab + row * 144 + seg * 32,      asrc + (size_t)row * D + seg * 8);     \
          cpa16(Ab + row * 144 + seg * 32 + 16, asrc + (size_t)row * D + seg * 8 + 4); } \
        { int row = tid >> 2, seg = tid & 3;                                   \
          cpa16(Bb + row * 80 + seg * 16, bsrc + (size_t)row * D + seg * 8); } \
        { int i2 = tid + 512; int row = i2 >> 2, seg = i2 & 3;                 \
          cpa16(Bb + row * 80 + seg * 16, bsrc + (size_t)row * D + seg * 8); } \
        asm volatile("cp.async.commit_group;" ::: "memory");                   \
    } while (0)

    for (int chunk = 0; chunk < 2; chunk++) {
        int n0 = chunk * 256;
        float acc[2][8][4];
        #pragma unroll
        for (int mt = 0; mt < 2; mt++)
            #pragma unroll
            for (int nt = 0; nt < 8; nt++)
                #pragma unroll
                for (int e = 0; e < 4; e++) acc[mt][nt][e] = 0.f;

        LOADH(0, 0, n0); LOADH(1, 1, n0); LOADH(2, 2, n0);

        for (int kc = 0; kc < NKC; kc++) {
            asm volatile("cp.async.wait_group 2;" ::: "memory");
            __syncthreads();
            if (kc + 3 < NKC) LOADH((kc + 3) & 3, kc + 3, n0);
            else asm volatile("cp.async.commit_group;" ::: "memory");

            const float* Aw = smf + ((kc & 3) * A_ST) / 4;
            uint32_t stBaseB = sb + B_BASE + (kc & 3) * B_ST;
            #pragma unroll
            for (int s2 = 0; s2 < 2; s2++) {
                int kf = s2 * 16;             /* float offset within A row */
                uint32_t af[2][4], bf[4][4];
                #pragma unroll
                for (int mt = 0; mt < 2; mt++) {
                    int r0 = wm * 32 + mt * 16 + g;
                    float2 f0 = *(const float2*)&Aw[r0 * 36 + kf + 2*c];
                    float2 f1 = *(const float2*)&Aw[(r0+8) * 36 + kf + 2*c];
                    float2 f2 = *(const float2*)&Aw[r0 * 36 + kf + 2*c + 8];
                    float2 f3 = *(const float2*)&Aw[(r0+8) * 36 + kf + 2*c + 8];
                    af[mt][0] = pack_h2(f0); af[mt][1] = pack_h2(f1);
                    af[mt][2] = pack_h2(f2); af[mt][3] = pack_h2(f3);
                }
                #pragma unroll
                for (int j = 0; j < 4; j++)
                    ldsm_x4(bf[j], stBaseB + bOff4[j] + s2 * 32);
                #pragma unroll
                for (int mt = 0; mt < 2; mt++)
                    #pragma unroll
                    for (int j = 0; j < 4; j++) {
                        mma_f16_16x8x16(acc[mt][2*j],     af[mt], &bf[j][0]);
                        mma_f16_16x8x16(acc[mt][2*j + 1], af[mt], &bf[j][2]);
                    }
            }
        }

        #pragma unroll
        for (int mt = 0; mt < 2; mt++) {
            #pragma unroll
            for (int nt = 0; nt < 8; nt++) {
                int s = chunk * 256 + wn * 64 + nt * 8 + 2 * c;
                float4 cp0 = scp[s], cp1 = scp[s + 1];
                float e0 = __expf(acc[mt][nt][0] + cp0.x);
                rs[mt][0][0] += e0; rs[mt][0][1] += e0 * cp0.y;
                rs[mt][0][2] += e0 * cp0.z; rs[mt][0][3] += e0 * cp0.w;
                float e1 = __expf(acc[mt][nt][1] + cp1.x);
                rs[mt][0][0] += e1; rs[mt][0][1] += e1 * cp1.y;
                rs[mt][0][2] += e1 * cp1.z; rs[mt][0][3] += e1 * cp1.w;
                float e2 = __expf(acc[mt][nt][2] + cp0.x);
                rs[mt][1][0] += e2; rs[mt][1][1] += e2 * cp0.y;
                rs[mt][1][2] += e2 * cp0.z; rs[mt][1][3] += e2 * cp0.w;
                float e3 = __expf(acc[mt][nt][3] + cp1.x);
                rs[mt][1][0] += e3; rs[mt][1][1] += e3 * cp1.y;
                rs[mt][1][2] += e3 * cp1.z; rs[mt][1][3] += e3 * cp1.w;
            }
        }
    }
#undef LOADH

    #pragma unroll
    for (int mt = 0; mt < 2; mt++)
        #pragma unroll
        for (int h = 0; h < 2; h++)
            #pragma unroll
            for (int e = 0; e < 4; e++) {
                float v = rs[mt][h][e];
                v += __shfl_xor_sync(0xFFFFFFFFu, v, 1);
                v += __shfl_xor_sync(0xFFFFFFFFu, v, 2);
                rs[mt][h][e] = v;
            }
    __syncthreads();
    if (c == 0) {
        #pragma unroll
        for (int mt = 0; mt < 2; mt++)
            #pragma unroll
            for (int h = 0; h < 2; h++) {
                int row = wm * 32 + mt * 16 + h * 8 + g;
                red4[wn * 128 + row] = make_float4(rs[mt][h][0], rs[mt][h][1],
                                                   rs[mt][h][2], rs[mt][h][3]);
            }
    }
    __syncthreads();
    if (tid < 128) {
        float4 a0 = red4[tid], a1 = red4[128 + tid],
               a2 = red4[256 + tid], a3 = red4[384 + tid];
        float den = a0.x + a1.x + a2.x + a3.x;
        float inv = 1.0f / den;
        g_pre[(size_t)b * M_TOT + m0 + tid] =
            make_float4((a0.y + a1.y + a2.y + a3.y) * inv,
                        (a0.z + a1.z + a2.z + a3.z) * inv,
                        (a0.w + a1.w + a2.w + a3.w) * inv, 0.f);
    }
}

/* ------------- heads ------------------------------------------------------- */
__global__ void k_heads(const float* __restrict__ b_law_d, const float* __restrict__ w_law1,
                        const float* __restrict__ b_law1,
                        const float* __restrict__ b_accu_d, const float* __restrict__ w_accu1,
                        const float* __restrict__ b_accu1,
                        const float* __restrict__ b_term_d, const float* __restrict__ w_term1,
                        const float* __restrict__ b_term1,
                        float* __restrict__ out) {
    int l = blockIdx.x, b = blockIdx.y, tid = threadIdx.x;
    float bl = b_law_d[0], ba = b_accu_d[0], bt = b_term_d[0];
    float s0 = 0, s1 = 0, s2 = 0;
    for (int r = tid; r < RR; r += 256) {
        float4 p = g_pre[(size_t)b * M_TOT + l * RR + r];
        s0 += tanhf(p.x + bl) * w_law1[r];
        s1 += tanhf(p.y + ba) * w_accu1[r];
        s2 += tanhf(p.z + bt) * w_term1[r];
    }
    __shared__ float sm[3][256];
    sm[0][tid] = s0; sm[1][tid] = s1; sm[2][tid] = s2;
    __syncthreads();
    for (int s = 128; s > 0; s >>= 1) {
        if (tid < s) for (int c = 0; c < 3; c++) sm[c][tid] += sm[c][tid + s];
        __syncthreads();
    }
    if (tid == 0) {
        out[b * LL + l] = sm[0][0] + b_law1[0];
        g_hax[b * LL + l] = tanhf(sm[1][0] + b_accu1[0]);
        g_htx[b * LL + l] = tanhf(sm[2][0] + b_term1[0]);
    }
}

__global__ void k_final(const float* __restrict__ Wa2, const float* __restrict__ ba2,
                        const float* __restrict__ Wt2, const float* __restrict__ bt2,
                        float* __restrict__ out) {
    int b = blockIdx.x, tid = threadIdx.x;
    if (tid < 119) {
        float s = ba2[tid];
        for (int l = 0; l < LL; l++) s += Wa2[tid * LL + l] * g_hax[b * LL + l];
        out[BBATCH*LL + b * 119 + tid] = s;
    } else if (tid < 130) {
        int j = tid - 119;
        float s = bt2[j];
        for (int l = 0; l < LL; l++) s += Wt2[j * LL + l] * g_htx[b * LL + l];
        out[BBATCH*LL + BBATCH*119 + b * 11 + j] = s;
    }
}

/* ---------------- launch --------------------------------------------------- */
extern "C" void kernel_launch(void* const* d_in, const int* in_sizes, int n_in,
                              void* d_out, int out_size) {
    const float* outp   = (const float*)d_in[0];
    const int*   amask  = (const int*)  d_in[1];
    const float* laws   = (const float*)d_in[2];
    const float* Wq     = (const float*)d_in[3];
    const float* bq     = (const float*)d_in[4];
    const float* Wk     = (const float*)d_in[5];
    const float* bk     = (const float*)d_in[6];
    const float* Wv     = (const float*)d_in[7];
    const float* bv     = (const float*)d_in[8];
    const float* w_law_d  = (const float*)d_in[9];
    const float* b_law_d  = (const float*)d_in[10];
    const float* w_law1   = (const float*)d_in[11];
    const float* b_law1   = (const float*)d_in[12];
    const float* w_accu_d = (const float*)d_in[13];
    const float* b_accu_d = (const float*)d_in[14];
    const float* w_accu1  = (const float*)d_in[15];
    const float* b_accu1  = (const float*)d_in[16];
    const float* W_accu2  = (const float*)d_in[17];
    const float* b_accu2  = (const float*)d_in[18];
    const float* w_term_d = (const float*)d_in[19];
    const float* b_term_d = (const float*)d_in[20];
    const float* w_term1  = (const float*)d_in[21];
    const float* b_term1  = (const float*)d_in[22];
    const float* W_term2  = (const float*)d_in[23];
    const float* b_term2  = (const float*)d_in[24];
    float* out = (float*)d_out;

    cudaFuncSetAttribute(k_big_h, cudaFuncAttributeMaxDynamicSharedMemorySize, SMEM_BIG);
    cudaFuncSetAttribute(k_wc_t,  cudaFuncAttributeMaxDynamicSharedMemorySize, SMEM_PREP);
    cudaFuncSetAttribute(k_fk2_t, cudaFuncAttributeMaxDynamicSharedMemorySize, SMEM_PREP);

    k_vecs<<<480, 256>>>(Wv, Wk, Wq, w_law_d, w_accu_d, w_term_d, bq, bk);
    k_scal<<<1, 256>>>(bk, bq, bv, w_law_d, w_accu_d, w_term_d);
    k_wc_t<<<dim3(D/64, D/64), 512, SMEM_PREP>>>(Wq, Wk);
    k_fk2_t<<<dim3(D/64, (BBATCH*SSEQ)/64), 512, SMEM_PREP>>>(outp);
    k_colpack<<<BBATCH*SSEQ/8, 256>>>(outp, amask);
    k_big_h<<<dim3(M_TOT/128, BBATCH), 512, SMEM_BIG>>>(laws);
    k_heads<<<dim3(LL, BBATCH), 256>>>(b_law_d, w_law1, b_law1,
                                       b_accu_d, w_accu1, b_accu1,
                                       b_term_d, w_term1, b_term1, out);
    k_final<<<BBATCH, 130>>>(W_accu2, b_accu2, W_term2, b_term2, out);
}